// round 10
// baseline (speedup 1.0000x reference)
#include <cuda_runtime.h>
#include <cuda_bf16.h>

#define HEADS 4
#define CHEAD 32
#define CIN   256
#define CHID  128
#define NTOK  4096
#define BATCH 4
#define BH    (BATCH * HEADS)

#define QSCALE ((float)(0.17677669529663687 * 1.4426950408889634))
#define FIXMAX 16.0f

// ---------------- device scratch ----------------
__device__ unsigned g_xhi[BATCH * CIN * NTOK / 2];
__device__ unsigned g_xlo[BATCH * CIN * NTOK / 2];
__device__ unsigned g_wqhi[384 * 256 / 2];
__device__ unsigned g_wqlo[384 * 256 / 2];
__device__ unsigned g_wohi[256 * 128 / 2];
__device__ unsigned g_wolo[256 * 128 / 2];
__device__ uint4 g_qhi[BH * NTOK * 4];
__device__ uint4 g_qlo[BH * NTOK * 4];
__device__ uint4 g_khi[BH * NTOK * 4];
__device__ uint4 g_klo[BH * NTOK * 4];
__device__ uint4 g_vhi[BH * NTOK * 4];
__device__ uint4 g_vlo[BH * NTOK * 4];
__device__ unsigned g_ahi[BATCH * NTOK * 64];
__device__ unsigned g_alo[BATCH * NTOK * 64];

// ---------------- helpers ----------------
__device__ __forceinline__ unsigned s2u(const void* p) {
    unsigned r;
    asm("{.reg .u64 t; cvta.to.shared.u64 t,%1; cvt.u32.u64 %0,t;}" : "=r"(r) : "l"(p));
    return r;
}
__device__ __forceinline__ float ex2f(float x) {
    float y; asm("ex2.approx.f32 %0,%1;" : "=f"(y) : "f"(x)); return y;
}
__device__ __forceinline__ void split2(float a, float b, unsigned& h, unsigned& l) {
    unsigned hh; asm("cvt.rn.bf16x2.f32 %0,%1,%2;" : "=r"(hh) : "f"(b), "f"(a));
    float ha = __uint_as_float(hh << 16);
    float hb = __uint_as_float(hh & 0xffff0000u);
    float ra = a - ha, rb = b - hb;
    unsigned ll; asm("cvt.rn.bf16x2.f32 %0,%1,%2;" : "=r"(ll) : "f"(rb), "f"(ra));
    h = hh; l = ll;
}

#define MMA_BF16(d, a0, a1, a2, a3, b0, b1) \
    asm volatile("mma.sync.aligned.m16n8k16.row.col.f32.bf16.bf16.f32 " \
        "{%0,%1,%2,%3},{%4,%5,%6,%7},{%8,%9},{%0,%1,%2,%3};" \
        : "+f"((d)[0]), "+f"((d)[1]), "+f"((d)[2]), "+f"((d)[3]) \
        : "r"(a0), "r"(a1), "r"(a2), "r"(a3), "r"(b0), "r"(b1))

#define LDSM_X4(r0, r1, r2, r3, a) \
    asm volatile("ldmatrix.sync.aligned.m8n8.x4.shared.b16 {%0,%1,%2,%3},[%4];" \
        : "=r"(r0), "=r"(r1), "=r"(r2), "=r"(r3) : "r"(a))
#define LDSM_X4_T(r0, r1, r2, r3, a) \
    asm volatile("ldmatrix.sync.aligned.m8n8.x4.trans.shared.b16 {%0,%1,%2,%3},[%4];" \
        : "=r"(r0), "=r"(r1), "=r"(r2), "=r"(r3) : "r"(a))

#define CP_ASYNC(dst, src) \
    asm volatile("cp.async.cg.shared.global [%0],[%1],16;" :: "r"(dst), "l"(src))
#define CP_COMMIT() asm volatile("cp.async.commit_group;")
#define CP_WAIT(n)  asm volatile("cp.async.wait_group %0;" :: "n"(n) : "memory")

// ============================================================================
// Kernel 0: split x / w_qkv / w_out into bf16 hi/lo pairs
// ============================================================================
#define NX2  (BATCH * CIN * NTOK / 2)
#define NWQ2 (384 * 256 / 2)
#define NWO2 (256 * 128 / 2)

__global__ __launch_bounds__(256) void split_kernel(const float* __restrict__ x,
                                                    const float* __restrict__ wq,
                                                    const float* __restrict__ wo)
{
    int i = blockIdx.x * 256 + threadIdx.x;
    if (i >= NX2 + NWQ2 + NWO2) return;
    const float2* src; unsigned *dh, *dl; int j;
    if (i < NX2)              { j = i;               src = (const float2*)x;  dh = g_xhi;  dl = g_xlo; }
    else if (i < NX2 + NWQ2)  { j = i - NX2;         src = (const float2*)wq; dh = g_wqhi; dl = g_wqlo; }
    else                      { j = i - NX2 - NWQ2;  src = (const float2*)wo; dh = g_wohi; dl = g_wolo; }
    float2 v = src[j];
    unsigned h, l; split2(v.x, v.y, h, l);
    dh[j] = h; dl[j] = l;
}

// ============================================================================
// Kernel 1: QKV projection, HMMA bf16x3 (unchanged)
// ============================================================================
#define QX_ROW 272
#define QXL    8704
#define QWH    17408
#define QW_ROW 80
#define QBUF   27648

__global__ __launch_bounds__(256) void qkv_mma()
{
    extern __shared__ unsigned char qs[];
    unsigned sb = s2u(qs);
    int tid = threadIdx.x, lane = tid & 31, wid = tid >> 5;
    int lrow = lane & 7, lmi = lane >> 3;
    int g = lane >> 2, tq = lane & 3;
    int n0 = blockIdx.x * 128, o0 = blockIdx.y * 64, b = blockIdx.z;

    float s[8][4];
    #pragma unroll
    for (int i = 0; i < 8; i++)
        #pragma unroll
        for (int j = 0; j < 4; j++) s[i][j] = 0.f;

    auto load_slice = [&](int ks, int buf) {
        unsigned bb = sb + buf * QBUF;
        #pragma unroll
        for (int i = tid; i < 1024; i += 256) {
            int arr = i >> 9, ch = i & 511, c = ch >> 4, c16 = ch & 15;
            unsigned dst = bb + arr * QXL + c * QX_ROW + c16 * 16;
            const char* src = (const char*)(arr ? g_xlo : g_xhi)
                + (((size_t)(b * CIN + ks * 32 + c)) * 2048 + (n0 >> 1) + c16 * 4) * 4;
            CP_ASYNC(dst, src);
        }
        #pragma unroll
        for (int i = tid; i < 512; i += 256) {
            int arr = i >> 8, ch = i & 255, o = ch >> 2, c16 = ch & 3;
            unsigned dst = bb + QWH + arr * 5120 + o * QW_ROW + c16 * 16;
            const char* src = (const char*)(arr ? g_wqlo : g_wqhi)
                + (((size_t)(o0 + o)) * 128 + ks * 16 + c16 * 4) * 4;
            CP_ASYNC(dst, src);
        }
        CP_COMMIT();
    };

    load_slice(0, 0);
    for (int ks = 0; ks < 8; ks++) {
        if (ks < 7) { load_slice(ks + 1, (ks + 1) & 1); CP_WAIT(1); }
        else        { CP_WAIT(0); }
        __syncthreads();

        unsigned xb = sb + (ks & 1) * QBUF;
        unsigned wb = xb + QWH;

        unsigned abase = xb + ((unsigned)((lane >> 4) * 8 + lrow)) * QX_ROW
                       + (wid * 16 + ((lane >> 3) & 1) * 8) * 2;
        unsigned axh0[4], axh1[4], axl0[4], axl1[4];
        LDSM_X4_T(axh0[0], axh0[1], axh0[2], axh0[3], abase);
        LDSM_X4_T(axh1[0], axh1[1], axh1[2], axh1[3], abase + 16 * QX_ROW);
        LDSM_X4_T(axl0[0], axl0[1], axl0[2], axl0[3], abase + QXL);
        LDSM_X4_T(axl1[0], axl1[1], axl1[2], axl1[3], abase + QXL + 16 * QX_ROW);

        unsigned bbase = wb + lrow * QW_ROW + lmi * 16;
        #pragma unroll
        for (int ot = 0; ot < 8; ot++) {
            unsigned bh0, bh1, bh2, bh3, bl0, bl1, bl2, bl3;
            unsigned ba = bbase + ot * (8 * QW_ROW);
            LDSM_X4(bh0, bh1, bh2, bh3, ba);
            LDSM_X4(bl0, bl1, bl2, bl3, ba + 5120);
            MMA_BF16(s[ot], axh0[0], axh0[1], axh0[2], axh0[3], bh0, bh1);
            MMA_BF16(s[ot], axl0[0], axl0[1], axl0[2], axl0[3], bh0, bh1);
            MMA_BF16(s[ot], axh0[0], axh0[1], axh0[2], axh0[3], bl0, bl1);
            MMA_BF16(s[ot], axh1[0], axh1[1], axh1[2], axh1[3], bh2, bh3);
            MMA_BF16(s[ot], axl1[0], axl1[1], axl1[2], axl1[3], bh2, bh3);
            MMA_BF16(s[ot], axh1[0], axh1[1], axh1[2], axh1[3], bl2, bl3);
        }
        __syncthreads();
    }

    int nr = n0 + wid * 16 + g;
    #pragma unroll
    for (int ot = 0; ot < 8; ot++) {
        int o = o0 + ot * 8 + 2 * tq;
        int kind = o >> 7, hh = (o >> 5) & 3, c = o & 31;
        unsigned* dh = (unsigned*)(kind == 0 ? g_qhi : (kind == 1 ? g_khi : g_vhi));
        unsigned* dl = (unsigned*)(kind == 0 ? g_qlo : (kind == 1 ? g_klo : g_vlo));
        float sc = (kind == 0) ? QSCALE : 1.f;
        size_t i0 = ((size_t)(b * HEADS + hh) * NTOK + nr) * 16 + (c >> 1);
        unsigned h0, l0;
        split2(s[ot][0] * sc, s[ot][1] * sc, h0, l0);
        dh[i0] = h0; dl[i0] = l0;
        split2(s[ot][2] * sc, s[ot][3] * sc, h0, l0);
        dh[i0 + 128] = h0; dl[i0 + 128] = l0;
    }
}

// ============================================================================
// Kernel 2: FlashAttention, intra-warp half-tile pipeline with STATIC register
// sets sA/sB (no dynamic indexing -> no spills). Fixed-max softmax.
// 64 queries / 128 threads per CTA; 3 smem buffers; 1 barrier per tile.
// ============================================================================
#define ROWB 80
#define ARRB (64 * ROWB)        // 5120
#define BUFB (4 * ARRB)         // 20480; 3 buffers = 61440
#define NTILE (NTOK / 64)

__global__ __launch_bounds__(128) void fattn_kernel()
{
    extern __shared__ unsigned char fsd[];
    unsigned sb = s2u(fsd);
    int tid = threadIdx.x;
    int lane = tid & 31, wid = tid >> 5;
    int qt = blockIdx.x, bh = blockIdx.y;
    int g = lane >> 2, tq = lane & 3;
    int lrow = lane & 7, lmi = lane >> 3;

    const uint4* srcs[4] = {
        g_khi + (size_t)bh * NTOK * 4, g_klo + (size_t)bh * NTOK * 4,
        g_vhi + (size_t)bh * NTOK * 4, g_vlo + (size_t)bh * NTOK * 4 };

    int c16 = tid & 3, r0 = tid >> 2;
    auto prefetch = [&](int t) {
        unsigned bb = sb + (t % 3) * BUFB;
        size_t goff = (size_t)t * 64 * 4;
        #pragma unroll
        for (int i = 0; i < 8; i++) {
            int arr = i >> 1, row = (r0 + i * 32) & 63;
            CP_ASYNC(bb + arr * ARRB + row * ROWB + c16 * 16,
                     srcs[arr] + goff + (size_t)row * 4 + c16);
        }
        CP_COMMIT();
    };

    prefetch(0);
    prefetch(1);

    // ---- Q fragments ----
    unsigned qh[2][4], ql[2][4];
    {
        int qa = qt * 64 + wid * 16 + g;
        const unsigned* ph = (const unsigned*)(g_qhi + ((size_t)bh * NTOK + qa) * 4);
        const unsigned* pl = (const unsigned*)(g_qlo + ((size_t)bh * NTOK + qa) * 4);
        #pragma unroll
        for (int kb = 0; kb < 2; kb++) {
            qh[kb][0] = ph[8 * kb + tq];       qh[kb][2] = ph[8 * kb + 4 + tq];
            qh[kb][1] = ph[128 + 8 * kb + tq]; qh[kb][3] = ph[128 + 8 * kb + 4 + tq];
            ql[kb][0] = pl[8 * kb + tq];       ql[kb][2] = pl[8 * kb + 4 + tq];
            ql[kb][1] = pl[128 + 8 * kb + tq]; ql[kb][3] = pl[128 + 8 * kb + 4 + tq];
        }
    }

    float o[4][4];
    #pragma unroll
    for (int i = 0; i < 4; i++)
        #pragma unroll
        for (int j = 0; j < 4; j++) o[i][j] = 0.f;
    float l_a = 0.f, l_b = 0.f;

    float sA[4][4], sB[4][4];

    // issue S-MMAs for half (T,h) into s (static array ref)
    auto smma = [&](float (&s)[4][4], int T, int h) {
        #pragma unroll
        for (int nb = 0; nb < 4; nb++)
            #pragma unroll
            for (int i = 0; i < 4; i++) s[nb][i] = 0.f;
        unsigned kb_base = sb + (T % 3) * BUFB;
        #pragma unroll
        for (int nb = 0; nb < 4; nb++) {
            unsigned kh0, kh1, kh2, kh3, kl0, kl1, kl2, kl3;
            unsigned ka = kb_base + (h * 32 + 8 * nb + lrow) * ROWB + lmi * 16;
            LDSM_X4(kh0, kh1, kh2, kh3, ka);
            LDSM_X4(kl0, kl1, kl2, kl3, ka + ARRB);
            MMA_BF16(s[nb], qh[0][0], qh[0][1], qh[0][2], qh[0][3], kh0, kh1);
            MMA_BF16(s[nb], qh[1][0], qh[1][1], qh[1][2], qh[1][3], kh2, kh3);
            MMA_BF16(s[nb], ql[0][0], ql[0][1], ql[0][2], ql[0][3], kh0, kh1);
            MMA_BF16(s[nb], ql[1][0], ql[1][1], ql[1][2], ql[1][3], kh2, kh3);
            MMA_BF16(s[nb], qh[0][0], qh[0][1], qh[0][2], qh[0][3], kl0, kl1);
            MMA_BF16(s[nb], qh[1][0], qh[1][1], qh[1][2], qh[1][3], kl2, kl3);
        }
    };

    // softmax + PV for half (T,h) from s
    auto proc = [&](float (&s)[4][4], int T, int h) {
        float sa = 0.f, sbm = 0.f;
        #pragma unroll
        for (int nb = 0; nb < 4; nb++) {
            s[nb][0] = ex2f(s[nb][0] - FIXMAX);
            s[nb][1] = ex2f(s[nb][1] - FIXMAX);
            s[nb][2] = ex2f(s[nb][2] - FIXMAX);
            s[nb][3] = ex2f(s[nb][3] - FIXMAX);
            sa += s[nb][0] + s[nb][1];
            sbm += s[nb][2] + s[nb][3];
        }
        l_a += sa; l_b += sbm;

        unsigned vbase = sb + (T % 3) * BUFB + 2 * ARRB;
        #pragma unroll
        for (int kb = 0; kb < 2; kb++) {
            unsigned ph[4], pl[4];
            split2(s[2 * kb][0],     s[2 * kb][1],     ph[0], pl[0]);
            split2(s[2 * kb][2],     s[2 * kb][3],     ph[1], pl[1]);
            split2(s[2 * kb + 1][0], s[2 * kb + 1][1], ph[2], pl[2]);
            split2(s[2 * kb + 1][2], s[2 * kb + 1][3], ph[3], pl[3]);
            #pragma unroll
            for (int cp = 0; cp < 2; cp++) {
                int oct = 2 * kb + (lmi & 1), chunk = 2 * cp + (lmi >> 1);
                unsigned va = vbase + (h * 32 + oct * 8 + lrow) * ROWB + chunk * 16;
                unsigned vh0, vh1, vh2, vh3, vl0, vl1, vl2, vl3;
                LDSM_X4_T(vh0, vh1, vh2, vh3, va);
                LDSM_X4_T(vl0, vl1, vl2, vl3, va + ARRB);
                MMA_BF16(o[2 * cp],     ph[0], ph[1], ph[2], ph[3], vh0, vh1);
                MMA_BF16(o[2 * cp + 1], ph[0], ph[1], ph[2], ph[3], vh2, vh3);
                MMA_BF16(o[2 * cp],     pl[0], pl[1], pl[2], pl[3], vh0, vh1);
                MMA_BF16(o[2 * cp + 1], pl[0], pl[1], pl[2], pl[3], vh2, vh3);
                MMA_BF16(o[2 * cp],     ph[0], ph[1], ph[2], ph[3], vl0, vl1);
                MMA_BF16(o[2 * cp + 1], ph[0], ph[1], ph[2], ph[3], vl2, vl3);
            }
        }
    };

    CP_WAIT(1);
    __syncthreads();
    smma(sA, 0, 0);

    for (int T = 0; T < NTILE - 1; T++) {
        CP_WAIT(0);          // tile T+1 resident
        __syncthreads();     // all warps done reading tile T-1
        if (T + 2 < NTILE) prefetch(T + 2);

        smma(sB, T, 1);      // queue tensor work...
        proc(sA, T, 0);      // ...overlap softmax ALU + PV of previous half
        smma(sA, T + 1, 0);
        proc(sB, T, 1);
    }
    CP_WAIT(0);
    __syncthreads();
    smma(sB, NTILE - 1, 1);
    proc(sA, NTILE - 1, 0);
    proc(sB, NTILE - 1, 1);

    // ---- single l reduction across key-quad lanes ----
    l_a += __shfl_xor_sync(0xffffffffu, l_a, 1);
    l_a += __shfl_xor_sync(0xffffffffu, l_a, 2);
    l_b += __shfl_xor_sync(0xffffffffu, l_b, 1);
    l_b += __shfl_xor_sync(0xffffffffu, l_b, 2);

    // ---- epilogue: normalize + split to bf16 hi/lo, [b][n][128] ----
    float inv_a = 1.f / l_a, inv_b = 1.f / l_b;
    int b = bh >> 2, h = bh & 3;
    int qa = qt * 64 + wid * 16 + g;
    #pragma unroll
    for (int nb = 0; nb < 4; nb++) {
        int c = h * 32 + nb * 8 + 2 * tq;
        size_t i0 = ((size_t)b * NTOK + qa) * 64 + (c >> 1);
        unsigned hA, lA;
        split2(o[nb][0] * inv_a, o[nb][1] * inv_a, hA, lA);
        g_ahi[i0] = hA; g_alo[i0] = lA;
        split2(o[nb][2] * inv_b, o[nb][3] * inv_b, hA, lA);
        g_ahi[i0 + 8 * 64] = hA; g_alo[i0 + 8 * 64] = lA;
    }
}

// ============================================================================
// Kernel 3: output projection, HMMA bf16x3 (unchanged)
// ============================================================================
#define OROW 272
#define OARR 17408

__global__ __launch_bounds__(256) void out_mma(const float* __restrict__ bias,
                                               float* __restrict__ out)
{
    extern __shared__ unsigned char osm[];
    unsigned sb = s2u(osm);
    int tid = threadIdx.x, lane = tid & 31, wid = tid >> 5;
    int lrow = lane & 7, lmi = lane >> 3;
    int g = lane >> 2, tq = lane & 3;
    int n0 = blockIdx.x * 64, o0 = blockIdx.y * 64, b = blockIdx.z;

    #pragma unroll
    for (int i = tid; i < 4096; i += 256) {
        int arr = i >> 10, ch = i & 1023, r = ch >> 4, c16 = ch & 15;
        unsigned dst = sb + arr * OARR + r * OROW + c16 * 16;
        const char* src;
        if (arr < 2)
            src = (const char*)(arr ? g_wolo : g_wohi)
                + (((size_t)(o0 + r)) * 64 + c16 * 4) * 4;
        else
            src = (const char*)(arr == 2 ? g_ahi : g_alo)
                + (((size_t)(b * NTOK + n0 + r)) * 64 + c16 * 4) * 4;
        CP_ASYNC(dst, src);
    }
    CP_COMMIT(); CP_WAIT(0);
    __syncthreads();

    int ow = wid >> 1, nh = wid & 1;
    float s[4][4];
    #pragma unroll
    for (int i = 0; i < 4; i++)
        #pragma unroll
        for (int j = 0; j < 4; j++) s[i][j] = 0.f;

    unsigned abase = sb + (ow * 16 + (lane & 15)) * OROW + (lane >> 4) * 16;
    unsigned bbase = sb + 2 * OARR + (nh * 32 + lrow) * OROW + lmi * 16;

    #pragma unroll
    for (int ksl = 0; ksl < 4; ksl++) {
        unsigned axh0[4], axh1[4], axl0[4], axl1[4];
        LDSM_X4(axh0[0], axh0[1], axh0[2], axh0[3], abase + ksl * 64);
        LDSM_X4(axh1[0], axh1[1], axh1[2], axh1[3], abase + ksl * 64 + 32);
        LDSM_X4(axl0[0], axl0[1], axl0[2], axl0[3], abase + OARR + ksl * 64);
        LDSM_X4(axl1[0], axl1[1], axl1[2], axl1[3], abase + OARR + ksl * 64 + 32);
        #pragma unroll
        for (int nt = 0; nt < 4; nt++) {
            unsigned bh0, bh1, bh2, bh3, bl0, bl1, bl2, bl3;
            unsigned ba = bbase + nt * (8 * OROW) + ksl * 64;
            LDSM_X4(bh0, bh1, bh2, bh3, ba);
            LDSM_X4(bl0, bl1, bl2, bl3, ba + OARR);
            MMA_BF16(s[nt], axh0[0], axh0[1], axh0[2], axh0[3], bh0, bh1);
            MMA_BF16(s[nt], axl0[0], axl0[1], axl0[2], axl0[3], bh0, bh1);
            MMA_BF16(s[nt], axh0[0], axh0[1], axh0[2], axh0[3], bl0, bl1);
            MMA_BF16(s[nt], axh1[0], axh1[1], axh1[2], axh1[3], bh2, bh3);
            MMA_BF16(s[nt], axl1[0], axl1[1], axl1[2], axl1[3], bh2, bh3);
            MMA_BF16(s[nt], axh1[0], axh1[1], axh1[2], axh1[3], bl2, bl3);
        }
    }

    int o = o0 + ow * 16 + g;
    float b0 = bias[o], b1 = bias[o + 8];
    #pragma unroll
    for (int nt = 0; nt < 4; nt++) {
        int n = n0 + nh * 32 + nt * 8 + 2 * tq;
        *(float2*)&out[((size_t)(b * CIN + o)) * NTOK + n] =
            make_float2(s[nt][0] + b0, s[nt][1] + b0);
        *(float2*)&out[((size_t)(b * CIN + o + 8)) * NTOK + n] =
            make_float2(s[nt][2] + b1, s[nt][3] + b1);
    }
}

// ============================================================================
extern "C" void kernel_launch(void* const* d_in, const int* in_sizes, int n_in,
                              void* d_out, int out_size)
{
    (void)in_sizes; (void)n_in; (void)out_size;
    const float* x     = (const float*)d_in[0];
    const float* w_qkv = (const float*)d_in[1];
    const float* w_out = (const float*)d_in[2];
    const float* b_out = (const float*)d_in[3];
    float* out = (float*)d_out;

    cudaFuncSetAttribute(qkv_mma, cudaFuncAttributeMaxDynamicSharedMemorySize, 2 * QBUF);
    cudaFuncSetAttribute(fattn_kernel, cudaFuncAttributeMaxDynamicSharedMemorySize, 3 * BUFB);
    cudaFuncSetAttribute(out_mma, cudaFuncAttributeMaxDynamicSharedMemorySize, 4 * OARR);

    int total = NX2 + NWQ2 + NWO2;
    split_kernel<<<(total + 255) / 256, 256>>>(x, w_qkv, w_out);
    qkv_mma<<<dim3(32, 6, 4), 256, 2 * QBUF>>>();
    fattn_kernel<<<dim3(NTOK / 64, BH), 128, 3 * BUFB>>>();
    out_mma<<<dim3(64, 4, 4), 256, 4 * OARR>>>(b_out, out);
}

// round 12
// speedup vs baseline: 1.0491x; 1.0491x over previous
#include <cuda_runtime.h>
#include <cuda_bf16.h>

#define HEADS 4
#define CHEAD 32
#define CIN   256
#define CHID  128
#define NTOK  4096
#define BATCH 4
#define BH    (BATCH * HEADS)

#define QSCALE ((float)(0.17677669529663687 * 1.4426950408889634))
#define FIXMAX 16.0f

// ---------------- device scratch ----------------
__device__ unsigned g_xhi[BATCH * CIN * NTOK / 2];
__device__ unsigned g_xlo[BATCH * CIN * NTOK / 2];
__device__ unsigned g_wqhi[384 * 256 / 2];
__device__ unsigned g_wqlo[384 * 256 / 2];
__device__ unsigned g_wohi[256 * 128 / 2];
__device__ unsigned g_wolo[256 * 128 / 2];
__device__ uint4 g_qhi[BH * NTOK * 4];
__device__ uint4 g_qlo[BH * NTOK * 4];
__device__ uint4 g_khi[BH * NTOK * 4];
__device__ uint4 g_klo[BH * NTOK * 4];
__device__ uint4 g_vhi[BH * NTOK * 4];
__device__ uint4 g_vlo[BH * NTOK * 4];
__device__ unsigned g_ahi[BATCH * NTOK * 64];
__device__ unsigned g_alo[BATCH * NTOK * 64];

// ---------------- helpers ----------------
__device__ __forceinline__ unsigned s2u(const void* p) {
    unsigned r;
    asm("{.reg .u64 t; cvta.to.shared.u64 t,%1; cvt.u32.u64 %0,t;}" : "=r"(r) : "l"(p));
    return r;
}
__device__ __forceinline__ float ex2f(float x) {
    float y; asm("ex2.approx.f32 %0,%1;" : "=f"(y) : "f"(x)); return y;
}
__device__ __forceinline__ void split2(float a, float b, unsigned& h, unsigned& l) {
    unsigned hh; asm("cvt.rn.bf16x2.f32 %0,%1,%2;" : "=r"(hh) : "f"(b), "f"(a));
    float ha = __uint_as_float(hh << 16);
    float hb = __uint_as_float(hh & 0xffff0000u);
    float ra = a - ha, rb = b - hb;
    unsigned ll; asm("cvt.rn.bf16x2.f32 %0,%1,%2;" : "=r"(ll) : "f"(rb), "f"(ra));
    h = hh; l = ll;
}

#define MMA_BF16(d, a0, a1, a2, a3, b0, b1) \
    asm volatile("mma.sync.aligned.m16n8k16.row.col.f32.bf16.bf16.f32 " \
        "{%0,%1,%2,%3},{%4,%5,%6,%7},{%8,%9},{%0,%1,%2,%3};" \
        : "+f"((d)[0]), "+f"((d)[1]), "+f"((d)[2]), "+f"((d)[3]) \
        : "r"(a0), "r"(a1), "r"(a2), "r"(a3), "r"(b0), "r"(b1))

#define LDSM_X4(r0, r1, r2, r3, a) \
    asm volatile("ldmatrix.sync.aligned.m8n8.x4.shared.b16 {%0,%1,%2,%3},[%4];" \
        : "=r"(r0), "=r"(r1), "=r"(r2), "=r"(r3) : "r"(a))
#define LDSM_X4_T(r0, r1, r2, r3, a) \
    asm volatile("ldmatrix.sync.aligned.m8n8.x4.trans.shared.b16 {%0,%1,%2,%3},[%4];" \
        : "=r"(r0), "=r"(r1), "=r"(r2), "=r"(r3) : "r"(a))

#define CP_ASYNC(dst, src) \
    asm volatile("cp.async.cg.shared.global [%0],[%1],16;" :: "r"(dst), "l"(src))
#define CP_COMMIT() asm volatile("cp.async.commit_group;")
#define CP_WAIT(n)  asm volatile("cp.async.wait_group %0;" :: "n"(n) : "memory")

// ============================================================================
// Kernel 0: split x / w_qkv / w_out into bf16 hi/lo pairs
// ============================================================================
#define NX2  (BATCH * CIN * NTOK / 2)
#define NWQ2 (384 * 256 / 2)
#define NWO2 (256 * 128 / 2)

__global__ __launch_bounds__(256) void split_kernel(const float* __restrict__ x,
                                                    const float* __restrict__ wq,
                                                    const float* __restrict__ wo)
{
    int i = blockIdx.x * 256 + threadIdx.x;
    if (i >= NX2 + NWQ2 + NWO2) return;
    const float2* src; unsigned *dh, *dl; int j;
    if (i < NX2)              { j = i;               src = (const float2*)x;  dh = g_xhi;  dl = g_xlo; }
    else if (i < NX2 + NWQ2)  { j = i - NX2;         src = (const float2*)wq; dh = g_wqhi; dl = g_wqlo; }
    else                      { j = i - NX2 - NWQ2;  src = (const float2*)wo; dh = g_wohi; dl = g_wolo; }
    float2 v = src[j];
    unsigned h, l; split2(v.x, v.y, h, l);
    dh[j] = h; dl[j] = l;
}

// ============================================================================
// Kernel 1: QKV projection, HMMA bf16x3 (unchanged)
// ============================================================================
#define QX_ROW 272
#define QXL    8704
#define QWH    17408
#define QW_ROW 80
#define QBUF   27648

__global__ __launch_bounds__(256) void qkv_mma()
{
    extern __shared__ unsigned char qs[];
    unsigned sb = s2u(qs);
    int tid = threadIdx.x, lane = tid & 31, wid = tid >> 5;
    int lrow = lane & 7, lmi = lane >> 3;
    int g = lane >> 2, tq = lane & 3;
    int n0 = blockIdx.x * 128, o0 = blockIdx.y * 64, b = blockIdx.z;

    float s[8][4];
    #pragma unroll
    for (int i = 0; i < 8; i++)
        #pragma unroll
        for (int j = 0; j < 4; j++) s[i][j] = 0.f;

    auto load_slice = [&](int ks, int buf) {
        unsigned bb = sb + buf * QBUF;
        #pragma unroll
        for (int i = tid; i < 1024; i += 256) {
            int arr = i >> 9, ch = i & 511, c = ch >> 4, c16 = ch & 15;
            unsigned dst = bb + arr * QXL + c * QX_ROW + c16 * 16;
            const char* src = (const char*)(arr ? g_xlo : g_xhi)
                + (((size_t)(b * CIN + ks * 32 + c)) * 2048 + (n0 >> 1) + c16 * 4) * 4;
            CP_ASYNC(dst, src);
        }
        #pragma unroll
        for (int i = tid; i < 512; i += 256) {
            int arr = i >> 8, ch = i & 255, o = ch >> 2, c16 = ch & 3;
            unsigned dst = bb + QWH + arr * 5120 + o * QW_ROW + c16 * 16;
            const char* src = (const char*)(arr ? g_wqlo : g_wqhi)
                + (((size_t)(o0 + o)) * 128 + ks * 16 + c16 * 4) * 4;
            CP_ASYNC(dst, src);
        }
        CP_COMMIT();
    };

    load_slice(0, 0);
    for (int ks = 0; ks < 8; ks++) {
        if (ks < 7) { load_slice(ks + 1, (ks + 1) & 1); CP_WAIT(1); }
        else        { CP_WAIT(0); }
        __syncthreads();

        unsigned xb = sb + (ks & 1) * QBUF;
        unsigned wb = xb + QWH;

        unsigned abase = xb + ((unsigned)((lane >> 4) * 8 + lrow)) * QX_ROW
                       + (wid * 16 + ((lane >> 3) & 1) * 8) * 2;
        unsigned axh0[4], axh1[4], axl0[4], axl1[4];
        LDSM_X4_T(axh0[0], axh0[1], axh0[2], axh0[3], abase);
        LDSM_X4_T(axh1[0], axh1[1], axh1[2], axh1[3], abase + 16 * QX_ROW);
        LDSM_X4_T(axl0[0], axl0[1], axl0[2], axl0[3], abase + QXL);
        LDSM_X4_T(axl1[0], axl1[1], axl1[2], axl1[3], abase + QXL + 16 * QX_ROW);

        unsigned bbase = wb + lrow * QW_ROW + lmi * 16;
        #pragma unroll
        for (int ot = 0; ot < 8; ot++) {
            unsigned bh0, bh1, bh2, bh3, bl0, bl1, bl2, bl3;
            unsigned ba = bbase + ot * (8 * QW_ROW);
            LDSM_X4(bh0, bh1, bh2, bh3, ba);
            LDSM_X4(bl0, bl1, bl2, bl3, ba + 5120);
            MMA_BF16(s[ot], axh0[0], axh0[1], axh0[2], axh0[3], bh0, bh1);
            MMA_BF16(s[ot], axl0[0], axl0[1], axl0[2], axl0[3], bh0, bh1);
            MMA_BF16(s[ot], axh0[0], axh0[1], axh0[2], axh0[3], bl0, bl1);
            MMA_BF16(s[ot], axh1[0], axh1[1], axh1[2], axh1[3], bh2, bh3);
            MMA_BF16(s[ot], axl1[0], axl1[1], axl1[2], axl1[3], bh2, bh3);
            MMA_BF16(s[ot], axh1[0], axh1[1], axh1[2], axh1[3], bl2, bl3);
        }
        __syncthreads();
    }

    int nr = n0 + wid * 16 + g;
    #pragma unroll
    for (int ot = 0; ot < 8; ot++) {
        int o = o0 + ot * 8 + 2 * tq;
        int kind = o >> 7, hh = (o >> 5) & 3, c = o & 31;
        unsigned* dh = (unsigned*)(kind == 0 ? g_qhi : (kind == 1 ? g_khi : g_vhi));
        unsigned* dl = (unsigned*)(kind == 0 ? g_qlo : (kind == 1 ? g_klo : g_vlo));
        float sc = (kind == 0) ? QSCALE : 1.f;
        size_t i0 = ((size_t)(b * HEADS + hh) * NTOK + nr) * 16 + (c >> 1);
        unsigned h0, l0;
        split2(s[ot][0] * sc, s[ot][1] * sc, h0, l0);
        dh[i0] = h0; dl[i0] = l0;
        split2(s[ot][2] * sc, s[ot][3] * sc, h0, l0);
        dh[i0 + 128] = h0; dl[i0 + 128] = l0;
    }
}

// ============================================================================
// Kernel 2: FlashAttention. 32 queries per WARP (two m16 row blocks) -> K/V
// fragments loaded once per warp serve both row blocks, halving smem reads
// per query. 128 q / 4 warps per CTA; 64-key tiles double-buffered; 32-key
// halves keep S register footprint static. Fixed-max softmax.
// ============================================================================
#define ROWB 80
#define ARRB (64 * ROWB)        // 5120
#define BUFB (4 * ARRB)         // 20480; 2 buffers = 40KB static

struct __align__(16) F3Smem { unsigned char kv[2][4][ARRB]; };

__global__ __launch_bounds__(128) void fattn_kernel()
{
    __shared__ F3Smem fs;
    unsigned sb = s2u(&fs);
    int tid = threadIdx.x;
    int lane = tid & 31, wid = tid >> 5;
    int qt = blockIdx.x, bh = blockIdx.y;
    int g = lane >> 2, tq = lane & 3;
    int lrow = lane & 7, lmi = lane >> 3;

    const uint4* srcs[4] = {
        g_khi + (size_t)bh * NTOK * 4, g_klo + (size_t)bh * NTOK * 4,
        g_vhi + (size_t)bh * NTOK * 4, g_vlo + (size_t)bh * NTOK * 4 };

    int c16 = tid & 3, r0 = tid >> 2;
    {
        #pragma unroll
        for (int i = 0; i < 8; i++) {
            int arr = i >> 1, row = (r0 + i * 32) & 63;
            unsigned dst = sb + arr * ARRB + row * ROWB + c16 * 16;
            CP_ASYNC(dst, srcs[arr] + (size_t)row * 4 + c16);
        }
        CP_COMMIT();
    }

    // ---- Q fragments: two row blocks of 16 queries ----
    unsigned qh[2][2][4], ql[2][2][4];
    #pragma unroll
    for (int rb = 0; rb < 2; rb++) {
        int qa = qt * 128 + wid * 32 + rb * 16 + g;
        const unsigned* ph = (const unsigned*)(g_qhi + ((size_t)bh * NTOK + qa) * 4);
        const unsigned* pl = (const unsigned*)(g_qlo + ((size_t)bh * NTOK + qa) * 4);
        #pragma unroll
        for (int kb = 0; kb < 2; kb++) {
            qh[rb][kb][0] = ph[8 * kb + tq];       qh[rb][kb][2] = ph[8 * kb + 4 + tq];
            qh[rb][kb][1] = ph[128 + 8 * kb + tq]; qh[rb][kb][3] = ph[128 + 8 * kb + 4 + tq];
            ql[rb][kb][0] = pl[8 * kb + tq];       ql[rb][kb][2] = pl[8 * kb + 4 + tq];
            ql[rb][kb][1] = pl[128 + 8 * kb + tq]; ql[rb][kb][3] = pl[128 + 8 * kb + 4 + tq];
        }
    }

    float o[2][4][4];
    #pragma unroll
    for (int rb = 0; rb < 2; rb++)
        #pragma unroll
        for (int i = 0; i < 4; i++)
            #pragma unroll
            for (int j = 0; j < 4; j++) o[rb][i][j] = 0.f;
    float la0 = 0.f, lb0 = 0.f, la1 = 0.f, lb1 = 0.f;

    int buf = 0;
    for (int kt = 0; kt < NTOK / 64; kt++) {
        if (kt < NTOK / 64 - 1) {
            unsigned bb = sb + (buf ^ 1) * BUFB;
            size_t goff = (size_t)(kt + 1) * 64 * 4;
            #pragma unroll
            for (int i = 0; i < 8; i++) {
                int arr = i >> 1, row = (r0 + i * 32) & 63;
                CP_ASYNC(bb + arr * ARRB + row * ROWB + c16 * 16,
                         srcs[arr] + goff + (size_t)row * 4 + c16);
            }
            CP_COMMIT();
            CP_WAIT(1);
        } else {
            CP_WAIT(0);
        }
        __syncthreads();

        unsigned kb_base = sb + buf * BUFB;
        unsigned vbase = kb_base + 2 * ARRB;

        #pragma unroll
        for (int h = 0; h < 2; h++) {           // 32-key halves
            float s0[4][4], s1[4][4];
            #pragma unroll
            for (int nb = 0; nb < 4; nb++)
                #pragma unroll
                for (int i = 0; i < 4; i++) { s0[nb][i] = 0.f; s1[nb][i] = 0.f; }

            // ---- S MMAs: K frags loaded once, used for both row blocks ----
            #pragma unroll
            for (int nb = 0; nb < 4; nb++) {
                unsigned kh0, kh1, kh2, kh3, kl0, kl1, kl2, kl3;
                unsigned ka = kb_base + (h * 32 + 8 * nb + lrow) * ROWB + lmi * 16;
                LDSM_X4(kh0, kh1, kh2, kh3, ka);
                LDSM_X4(kl0, kl1, kl2, kl3, ka + ARRB);
                MMA_BF16(s0[nb], qh[0][0][0], qh[0][0][1], qh[0][0][2], qh[0][0][3], kh0, kh1);
                MMA_BF16(s0[nb], qh[0][1][0], qh[0][1][1], qh[0][1][2], qh[0][1][3], kh2, kh3);
                MMA_BF16(s0[nb], ql[0][0][0], ql[0][0][1], ql[0][0][2], ql[0][0][3], kh0, kh1);
                MMA_BF16(s0[nb], ql[0][1][0], ql[0][1][1], ql[0][1][2], ql[0][1][3], kh2, kh3);
                MMA_BF16(s0[nb], qh[0][0][0], qh[0][0][1], qh[0][0][2], qh[0][0][3], kl0, kl1);
                MMA_BF16(s0[nb], qh[0][1][0], qh[0][1][1], qh[0][1][2], qh[0][1][3], kl2, kl3);
                MMA_BF16(s1[nb], qh[1][0][0], qh[1][0][1], qh[1][0][2], qh[1][0][3], kh0, kh1);
                MMA_BF16(s1[nb], qh[1][1][0], qh[1][1][1], qh[1][1][2], qh[1][1][3], kh2, kh3);
                MMA_BF16(s1[nb], ql[1][0][0], ql[1][0][1], ql[1][0][2], ql[1][0][3], kh0, kh1);
                MMA_BF16(s1[nb], ql[1][1][0], ql[1][1][1], ql[1][1][2], ql[1][1][3], kh2, kh3);
                MMA_BF16(s1[nb], qh[1][0][0], qh[1][0][1], qh[1][0][2], qh[1][0][3], kl0, kl1);
                MMA_BF16(s1[nb], qh[1][1][0], qh[1][1][1], qh[1][1][2], qh[1][1][3], kl2, kl3);
            }

            // ---- fixed-max softmax ----
            #pragma unroll
            for (int nb = 0; nb < 4; nb++) {
                s0[nb][0] = ex2f(s0[nb][0] - FIXMAX);
                s0[nb][1] = ex2f(s0[nb][1] - FIXMAX);
                s0[nb][2] = ex2f(s0[nb][2] - FIXMAX);
                s0[nb][3] = ex2f(s0[nb][3] - FIXMAX);
                la0 += s0[nb][0] + s0[nb][1];
                lb0 += s0[nb][2] + s0[nb][3];
                s1[nb][0] = ex2f(s1[nb][0] - FIXMAX);
                s1[nb][1] = ex2f(s1[nb][1] - FIXMAX);
                s1[nb][2] = ex2f(s1[nb][2] - FIXMAX);
                s1[nb][3] = ex2f(s1[nb][3] - FIXMAX);
                la1 += s1[nb][0] + s1[nb][1];
                lb1 += s1[nb][2] + s1[nb][3];
            }

            // ---- PV: V frags loaded once, used for both row blocks ----
            #pragma unroll
            for (int kb = 0; kb < 2; kb++) {
                unsigned p0h[4], p0l[4], p1h[4], p1l[4];
                split2(s0[2 * kb][0],     s0[2 * kb][1],     p0h[0], p0l[0]);
                split2(s0[2 * kb][2],     s0[2 * kb][3],     p0h[1], p0l[1]);
                split2(s0[2 * kb + 1][0], s0[2 * kb + 1][1], p0h[2], p0l[2]);
                split2(s0[2 * kb + 1][2], s0[2 * kb + 1][3], p0h[3], p0l[3]);
                split2(s1[2 * kb][0],     s1[2 * kb][1],     p1h[0], p1l[0]);
                split2(s1[2 * kb][2],     s1[2 * kb][3],     p1h[1], p1l[1]);
                split2(s1[2 * kb + 1][0], s1[2 * kb + 1][1], p1h[2], p1l[2]);
                split2(s1[2 * kb + 1][2], s1[2 * kb + 1][3], p1h[3], p1l[3]);
                #pragma unroll
                for (int cp = 0; cp < 2; cp++) {
                    int oct = 2 * kb + (lmi & 1), chunk = 2 * cp + (lmi >> 1);
                    unsigned va = vbase + (h * 32 + oct * 8 + lrow) * ROWB + chunk * 16;
                    unsigned vh0, vh1, vh2, vh3, vl0, vl1, vl2, vl3;
                    LDSM_X4_T(vh0, vh1, vh2, vh3, va);
                    LDSM_X4_T(vl0, vl1, vl2, vl3, va + ARRB);
                    MMA_BF16(o[0][2 * cp],     p0h[0], p0h[1], p0h[2], p0h[3], vh0, vh1);
                    MMA_BF16(o[0][2 * cp + 1], p0h[0], p0h[1], p0h[2], p0h[3], vh2, vh3);
                    MMA_BF16(o[0][2 * cp],     p0l[0], p0l[1], p0l[2], p0l[3], vh0, vh1);
                    MMA_BF16(o[0][2 * cp + 1], p0l[0], p0l[1], p0l[2], p0l[3], vh2, vh3);
                    MMA_BF16(o[0][2 * cp],     p0h[0], p0h[1], p0h[2], p0h[3], vl0, vl1);
                    MMA_BF16(o[0][2 * cp + 1], p0h[0], p0h[1], p0h[2], p0h[3], vl2, vl3);
                    MMA_BF16(o[1][2 * cp],     p1h[0], p1h[1], p1h[2], p1h[3], vh0, vh1);
                    MMA_BF16(o[1][2 * cp + 1], p1h[0], p1h[1], p1h[2], p1h[3], vh2, vh3);
                    MMA_BF16(o[1][2 * cp],     p1l[0], p1l[1], p1l[2], p1l[3], vh0, vh1);
                    MMA_BF16(o[1][2 * cp + 1], p1l[0], p1l[1], p1l[2], p1l[3], vh2, vh3);
                    MMA_BF16(o[1][2 * cp],     p1h[0], p1h[1], p1h[2], p1h[3], vl0, vl1);
                    MMA_BF16(o[1][2 * cp + 1], p1h[0], p1h[1], p1h[2], p1h[3], vl2, vl3);
                }
            }
        }

        __syncthreads();
        buf ^= 1;
    }

    // ---- l reductions (once) ----
    la0 += __shfl_xor_sync(0xffffffffu, la0, 1);
    la0 += __shfl_xor_sync(0xffffffffu, la0, 2);
    lb0 += __shfl_xor_sync(0xffffffffu, lb0, 1);
    lb0 += __shfl_xor_sync(0xffffffffu, lb0, 2);
    la1 += __shfl_xor_sync(0xffffffffu, la1, 1);
    la1 += __shfl_xor_sync(0xffffffffu, la1, 2);
    lb1 += __shfl_xor_sync(0xffffffffu, lb1, 1);
    lb1 += __shfl_xor_sync(0xffffffffu, lb1, 2);

    // ---- epilogue: normalize + split to bf16 hi/lo, [b][n][128] ----
    int b = bh >> 2, h = bh & 3;
    #pragma unroll
    for (int rb = 0; rb < 2; rb++) {
        float inv_a = 1.f / (rb ? la1 : la0);
        float inv_b = 1.f / (rb ? lb1 : lb0);
        int qa = qt * 128 + wid * 32 + rb * 16 + g;
        #pragma unroll
        for (int nb = 0; nb < 4; nb++) {
            int c = h * 32 + nb * 8 + 2 * tq;
            size_t i0 = ((size_t)b * NTOK + qa) * 64 + (c >> 1);
            unsigned hA, lA;
            split2(o[rb][nb][0] * inv_a, o[rb][nb][1] * inv_a, hA, lA);
            g_ahi[i0] = hA; g_alo[i0] = lA;
            split2(o[rb][nb][2] * inv_b, o[rb][nb][3] * inv_b, hA, lA);
            g_ahi[i0 + 8 * 64] = hA; g_alo[i0 + 8 * 64] = lA;
        }
    }
}

// ============================================================================
// Kernel 3: output projection, HMMA bf16x3 (unchanged)
// ============================================================================
#define OROW 272
#define OARR 17408

__global__ __launch_bounds__(256) void out_mma(const float* __restrict__ bias,
                                               float* __restrict__ out)
{
    extern __shared__ unsigned char osm[];
    unsigned sb = s2u(osm);
    int tid = threadIdx.x, lane = tid & 31, wid = tid >> 5;
    int lrow = lane & 7, lmi = lane >> 3;
    int g = lane >> 2, tq = lane & 3;
    int n0 = blockIdx.x * 64, o0 = blockIdx.y * 64, b = blockIdx.z;

    #pragma unroll
    for (int i = tid; i < 4096; i += 256) {
        int arr = i >> 10, ch = i & 1023, r = ch >> 4, c16 = ch & 15;
        unsigned dst = sb + arr * OARR + r * OROW + c16 * 16;
        const char* src;
        if (arr < 2)
            src = (const char*)(arr ? g_wolo : g_wohi)
                + (((size_t)(o0 + r)) * 64 + c16 * 4) * 4;
        else
            src = (const char*)(arr == 2 ? g_ahi : g_alo)
                + (((size_t)(b * NTOK + n0 + r)) * 64 + c16 * 4) * 4;
        CP_ASYNC(dst, src);
    }
    CP_COMMIT(); CP_WAIT(0);
    __syncthreads();

    int ow = wid >> 1, nh = wid & 1;
    float s[4][4];
    #pragma unroll
    for (int i = 0; i < 4; i++)
        #pragma unroll
        for (int j = 0; j < 4; j++) s[i][j] = 0.f;

    unsigned abase = sb + (ow * 16 + (lane & 15)) * OROW + (lane >> 4) * 16;
    unsigned bbase = sb + 2 * OARR + (nh * 32 + lrow) * OROW + lmi * 16;

    #pragma unroll
    for (int ksl = 0; ksl < 4; ksl++) {
        unsigned axh0[4], axh1[4], axl0[4], axl1[4];
        LDSM_X4(axh0[0], axh0[1], axh0[2], axh0[3], abase + ksl * 64);
        LDSM_X4(axh1[0], axh1[1], axh1[2], axh1[3], abase + ksl * 64 + 32);
        LDSM_X4(axl0[0], axl0[1], axl0[2], axl0[3], abase + OARR + ksl * 64);
        LDSM_X4(axl1[0], axl1[1], axl1[2], axl1[3], abase + OARR + ksl * 64 + 32);
        #pragma unroll
        for (int nt = 0; nt < 4; nt++) {
            unsigned bh0, bh1, bh2, bh3, bl0, bl1, bl2, bl3;
            unsigned ba = bbase + nt * (8 * OROW) + ksl * 64;
            LDSM_X4(bh0, bh1, bh2, bh3, ba);
            LDSM_X4(bl0, bl1, bl2, bl3, ba + OARR);
            MMA_BF16(s[nt], axh0[0], axh0[1], axh0[2], axh0[3], bh0, bh1);
            MMA_BF16(s[nt], axl0[0], axl0[1], axl0[2], axl0[3], bh0, bh1);
            MMA_BF16(s[nt], axh0[0], axh0[1], axh0[2], axh0[3], bl0, bl1);
            MMA_BF16(s[nt], axh1[0], axh1[1], axh1[2], axh1[3], bh2, bh3);
            MMA_BF16(s[nt], axl1[0], axl1[1], axl1[2], axl1[3], bh2, bh3);
            MMA_BF16(s[nt], axh1[0], axh1[1], axh1[2], axh1[3], bl2, bl3);
        }
    }

    int o = o0 + ow * 16 + g;
    float b0 = bias[o], b1 = bias[o + 8];
    #pragma unroll
    for (int nt = 0; nt < 4; nt++) {
        int n = n0 + nh * 32 + nt * 8 + 2 * tq;
        *(float2*)&out[((size_t)(b * CIN + o)) * NTOK + n] =
            make_float2(s[nt][0] + b0, s[nt][1] + b0);
        *(float2*)&out[((size_t)(b * CIN + o + 8)) * NTOK + n] =
            make_float2(s[nt][2] + b1, s[nt][3] + b1);
    }
}

// ============================================================================
extern "C" void kernel_launch(void* const* d_in, const int* in_sizes, int n_in,
                              void* d_out, int out_size)
{
    (void)in_sizes; (void)n_in; (void)out_size;
    const float* x     = (const float*)d_in[0];
    const float* w_qkv = (const float*)d_in[1];
    const float* w_out = (const float*)d_in[2];
    const float* b_out = (const float*)d_in[3];
    float* out = (float*)d_out;

    cudaFuncSetAttribute(qkv_mma, cudaFuncAttributeMaxDynamicSharedMemorySize, 2 * QBUF);
    cudaFuncSetAttribute(out_mma, cudaFuncAttributeMaxDynamicSharedMemorySize, 4 * OARR);

    int total = NX2 + NWQ2 + NWO2;
    split_kernel<<<(total + 255) / 256, 256>>>(x, w_qkv, w_out);
    qkv_mma<<<dim3(32, 6, 4), 256, 2 * QBUF>>>();
    fattn_kernel<<<dim3(NTOK / 128, BH), 128>>>();
    out_mma<<<dim3(64, 4, 4), 256, 4 * OARR>>>(b_out, out);
}